// round 1
// baseline (speedup 1.0000x reference)
#include <cuda_runtime.h>

#define NN 50000
#define NE 800000
#define DD 256
#define OO 32

// ---------------- scratch (no allocs allowed -> device globals) ----------------
__device__ float g_h1[NN * DD];   // h @ W + b
__device__ float g_nb[NN * DD];   // h1 @ Wn + bn
__device__ float g_agg[NN * DD];  // APPNP aggregation
__device__ float g_h[NN * DD];    // layer output
__device__ float g_dinv[NN];
__device__ int   g_deg[NN];

// ---------------- degree / dinv ----------------
__global__ void k_zero_deg() {
    int i = blockIdx.x * blockDim.x + threadIdx.x;
    if (i < NN) g_deg[i] = 0;
}

__global__ void k_count(const int* __restrict__ row) {
    int e = blockIdx.x * blockDim.x + threadIdx.x;
    if (e < NE) atomicAdd(&g_deg[row[e]], 1);
}

__global__ void k_dinv() {
    int i = blockIdx.x * blockDim.x + threadIdx.x;
    if (i < NN) g_dinv[i] = rsqrtf((float)g_deg[i] + 1.0f);  // +1 self-loop
}

// ---------------- SGEMM: C[M x Nc] = A[M x 256] @ B[256 x Nc] + bias ----------------
// BM=BN=128, BK=16, 256 threads, 8x8 per thread. Nc must be a multiple of 128.
__global__ __launch_bounds__(256) void k_sgemm(
    const float* __restrict__ A, const float* __restrict__ B,
    const float* __restrict__ bias, float* __restrict__ C, int M, int Nc)
{
    __shared__ float As[16][128];   // transposed: As[k][m]
    __shared__ float Bs[16][128];   // Bs[k][n]

    const int tid = threadIdx.x;
    const int tr = tid >> 4;        // 0..15 (row group)
    const int tc = tid & 15;        // 0..15 (col group)
    const int brow = blockIdx.x;
    const int bcol = blockIdx.y;

    const int aRow = tid >> 2;      // 0..63
    const int aK4  = tid & 3;       // 0..3
    const int bK   = tid >> 5;      // 0..7
    const int bN4  = tid & 31;      // 0..31

    float acc[8][8];
    #pragma unroll
    for (int i = 0; i < 8; i++)
        #pragma unroll
        for (int j = 0; j < 8; j++) acc[i][j] = 0.0f;

    const float* Ab = A + (size_t)brow * 128 * 256;
    const float* Bb = B + bcol * 128;

    for (int kt = 0; kt < 16; kt++) {
        // ---- load A tile (128x16), store transposed ----
        #pragma unroll
        for (int h = 0; h < 2; h++) {
            int m = aRow + h * 64;
            int gm = brow * 128 + m;
            float4 v = make_float4(0.f, 0.f, 0.f, 0.f);
            if (gm < M)
                v = *(const float4*)(Ab + (size_t)m * 256 + kt * 16 + aK4 * 4);
            As[aK4 * 4 + 0][m] = v.x;
            As[aK4 * 4 + 1][m] = v.y;
            As[aK4 * 4 + 2][m] = v.z;
            As[aK4 * 4 + 3][m] = v.w;
        }
        // ---- load B tile (16x128) ----
        #pragma unroll
        for (int h = 0; h < 2; h++) {
            int k = bK + h * 8;
            float4 v = *(const float4*)(Bb + (size_t)(kt * 16 + k) * Nc + bN4 * 4);
            *(float4*)(&Bs[k][bN4 * 4]) = v;
        }
        __syncthreads();

        #pragma unroll
        for (int bk = 0; bk < 16; bk++) {
            float4 a0 = *(const float4*)(&As[bk][tr * 8]);
            float4 a1 = *(const float4*)(&As[bk][tr * 8 + 4]);
            float4 b0 = *(const float4*)(&Bs[bk][tc * 8]);
            float4 b1 = *(const float4*)(&Bs[bk][tc * 8 + 4]);
            float av[8] = {a0.x, a0.y, a0.z, a0.w, a1.x, a1.y, a1.z, a1.w};
            float bv[8] = {b0.x, b0.y, b0.z, b0.w, b1.x, b1.y, b1.z, b1.w};
            #pragma unroll
            for (int i = 0; i < 8; i++)
                #pragma unroll
                for (int j = 0; j < 8; j++)
                    acc[i][j] += av[i] * bv[j];
        }
        __syncthreads();
    }

    // ---- epilogue: + bias, store ----
    float4 bb0 = *(const float4*)(bias + bcol * 128 + tc * 8);
    float4 bb1 = *(const float4*)(bias + bcol * 128 + tc * 8 + 4);
    float bvv[8] = {bb0.x, bb0.y, bb0.z, bb0.w, bb1.x, bb1.y, bb1.z, bb1.w};

    #pragma unroll
    for (int i = 0; i < 8; i++) {
        int gm = brow * 128 + tr * 8 + i;
        if (gm < M) {
            float4 o0 = make_float4(acc[i][0] + bvv[0], acc[i][1] + bvv[1],
                                    acc[i][2] + bvv[2], acc[i][3] + bvv[3]);
            float4 o1 = make_float4(acc[i][4] + bvv[4], acc[i][5] + bvv[5],
                                    acc[i][6] + bvv[6], acc[i][7] + bvv[7]);
            float* cp = C + (size_t)gm * Nc + bcol * 128 + tc * 8;
            *(float4*)(cp)     = o0;
            *(float4*)(cp + 4) = o1;
        }
    }
}

// ---------------- self-loop init: agg[i] = dinv[i]^2 * nb[i] ----------------
__global__ void k_init_agg() {
    int idx = blockIdx.x * blockDim.x + threadIdx.x;   // over NN*64 float4
    if (idx >= NN * 64) return;
    int i = idx >> 6;
    float s = g_dinv[i];
    s = s * s;
    float4 v = ((const float4*)g_nb)[idx];
    v.x *= s; v.y *= s; v.z *= s; v.w *= s;
    ((float4*)g_agg)[idx] = v;
}

// ---------------- edge scatter: agg[row] += dinv[row]*dinv[col]*nb[col] ----------------
// one warp per edge, vectorized L2 reductions (red.global.add.v4.f32, sm_90+)
__global__ void k_scatter(const int* __restrict__ row, const int* __restrict__ col) {
    int gw = (blockIdx.x * blockDim.x + threadIdx.x) >> 5;
    int lane = threadIdx.x & 31;
    if (gw >= NE) return;
    int r = __ldg(row + gw);
    int c = __ldg(col + gw);
    float s = g_dinv[r] * g_dinv[c];
    const float4* src = (const float4*)g_nb + (size_t)c * 64;
    float4* dst = (float4*)g_agg + (size_t)r * 64;
    #pragma unroll
    for (int h = 0; h < 2; h++) {
        float4 v = __ldg(src + lane + h * 32);
        v.x *= s; v.y *= s; v.z *= s; v.w *= s;
        asm volatile("red.global.add.v4.f32 [%0], {%1, %2, %3, %4};"
                     :: "l"(dst + lane + h * 32),
                        "f"(v.x), "f"(v.y), "f"(v.z), "f"(v.w)
                     : "memory");
    }
}

// ---------------- combine + residual + L2 normalize + relu -> g_h ----------------
// v = h1 + 0.5*agg + 0.5*nb ; h = relu(v / max(||v||2, 1e-12))
__global__ __launch_bounds__(256) void k_combine() {
    int i = blockIdx.x;
    int t = threadIdx.x;
    size_t idx = (size_t)i * 256 + t;
    float v = g_h1[idx] + 0.5f * g_agg[idx] + 0.5f * g_nb[idx];

    float ss = v * v;
    #pragma unroll
    for (int o = 16; o; o >>= 1) ss += __shfl_xor_sync(0xffffffffu, ss, o);

    __shared__ float ws[8];
    __shared__ float sscale;
    if ((t & 31) == 0) ws[t >> 5] = ss;
    __syncthreads();
    if (t == 0) {
        float s = ws[0] + ws[1] + ws[2] + ws[3] + ws[4] + ws[5] + ws[6] + ws[7];
        sscale = 1.0f / fmaxf(sqrtf(s), 1e-12f);
    }
    __syncthreads();
    g_h[idx] = fmaxf(v * sscale, 0.0f);
}

// ---------------- final: out[M x 32] = g_h @ W2 + b2 ----------------
// block = 256 threads = 64 rows x 4 col-groups of 8; W2 staged in shared.
__global__ __launch_bounds__(256) void k_final(
    const float* __restrict__ W2, const float* __restrict__ b2,
    float* __restrict__ out, int M)
{
    __shared__ float Ws[256 * 32];
    int tid = threadIdx.x;
    #pragma unroll
    for (int i = 0; i < 8; i++)
        ((float4*)Ws)[tid + i * 256] = ((const float4*)W2)[tid + i * 256];
    __syncthreads();

    int r = blockIdx.x * 64 + (tid >> 2);
    int cg = (tid & 3) * 8;
    if (r >= M) return;

    const float4* Arow = (const float4*)(g_h + (size_t)r * 256);
    float acc[8];
    #pragma unroll
    for (int j = 0; j < 8; j++) acc[j] = 0.0f;

    #pragma unroll 4
    for (int k4 = 0; k4 < 64; k4++) {
        float4 a = __ldg(Arow + k4);
        float av[4] = {a.x, a.y, a.z, a.w};
        #pragma unroll
        for (int u = 0; u < 4; u++) {
            const float* wrow = Ws + (k4 * 4 + u) * 32 + cg;
            float4 w0 = *(const float4*)(wrow);
            float4 w1 = *(const float4*)(wrow + 4);
            acc[0] += av[u] * w0.x;
            acc[1] += av[u] * w0.y;
            acc[2] += av[u] * w0.z;
            acc[3] += av[u] * w0.w;
            acc[4] += av[u] * w1.x;
            acc[5] += av[u] * w1.y;
            acc[6] += av[u] * w1.z;
            acc[7] += av[u] * w1.w;
        }
    }
    float4 o0 = make_float4(acc[0] + __ldg(b2 + cg + 0), acc[1] + __ldg(b2 + cg + 1),
                            acc[2] + __ldg(b2 + cg + 2), acc[3] + __ldg(b2 + cg + 3));
    float4 o1 = make_float4(acc[4] + __ldg(b2 + cg + 4), acc[5] + __ldg(b2 + cg + 5),
                            acc[6] + __ldg(b2 + cg + 6), acc[7] + __ldg(b2 + cg + 7));
    float* op = out + (size_t)r * 32 + cg;
    *(float4*)(op)     = o0;
    *(float4*)(op + 4) = o1;
}

// ---------------- host ----------------
extern "C" void kernel_launch(void* const* d_in, const int* in_sizes, int n_in,
                              void* d_out, int out_size)
{
    const float* x   = (const float*)d_in[0];
    const int*   ei  = (const int*)d_in[1];
    const int*   row = ei;
    const int*   col = ei + NE;
    const float* W[2]  = {(const float*)d_in[2], (const float*)d_in[6]};
    const float* bW[2] = {(const float*)d_in[3], (const float*)d_in[7]};
    const float* Wn[2] = {(const float*)d_in[4], (const float*)d_in[8]};
    const float* bn[2] = {(const float*)d_in[5], (const float*)d_in[9]};
    const float* W2 = (const float*)d_in[10];
    const float* b2 = (const float*)d_in[11];
    float* out = (float*)d_out;

    float *h1, *nb, *h;
    cudaGetSymbolAddress((void**)&h1, g_h1);
    cudaGetSymbolAddress((void**)&nb, g_nb);
    cudaGetSymbolAddress((void**)&h,  g_h);

    // degrees + dinv
    k_zero_deg<<<(NN + 255) / 256, 256>>>();
    k_count<<<(NE + 255) / 256, 256>>>(row);
    k_dinv<<<(NN + 255) / 256, 256>>>();

    const float* hin = x;
    dim3 gg((NN + 127) / 128, DD / 128);
    for (int l = 0; l < 2; l++) {
        k_sgemm<<<gg, 256>>>(hin, W[l], bW[l], h1, NN, DD);
        k_sgemm<<<gg, 256>>>(h1, Wn[l], bn[l], nb, NN, DD);
        k_init_agg<<<(NN * 64 + 255) / 256, 256>>>();
        k_scatter<<<(NE * 32 + 255) / 256, 256>>>(row, col);
        k_combine<<<NN, 256>>>();
        hin = h;
    }
    k_final<<<(NN + 63) / 64, 256>>>(W2, b2, out, NN);
}

// round 13
// speedup vs baseline: 1.2973x; 1.2973x over previous
#include <cuda_runtime.h>
#include <cuda_bf16.h>
#include <cstdint>

#define NN 50000
#define NE 800000
#define DD 256
#define OO 32

// ---------------- scratch ----------------
__device__ float g_h1[NN * DD];
__device__ float g_nb[NN * DD];
__device__ float g_agg[NN * DD];
__device__ float g_h[NN * DD];
__device__ float g_dinv[NN];
__device__ int   g_deg[NN];

// ================= helpers =================
__device__ __forceinline__ uint32_t smem_u32(const void* p) {
    uint32_t a;
    asm("{ .reg .u64 t; cvta.to.shared.u64 t, %1; cvt.u32.u64 %0, t; }" : "=r"(a) : "l"(p));
    return a;
}
__device__ __forceinline__ uint32_t pack2(float a, float b) {
    __nv_bfloat162 h = __floats2bfloat162_rn(a, b);
    return *(uint32_t*)&h;
}

#define LDSM_X4(r0, r1, r2, r3, addr) \
    asm volatile("ldmatrix.sync.aligned.m8n8.x4.shared.b16 {%0,%1,%2,%3}, [%4];" \
                 : "=r"(r0), "=r"(r1), "=r"(r2), "=r"(r3) : "r"(addr))
#define LDSM_X2T(r0, r1, addr) \
    asm volatile("ldmatrix.sync.aligned.m8n8.x2.trans.shared.b16 {%0,%1}, [%2];" \
                 : "=r"(r0), "=r"(r1) : "r"(addr))
#define MMA_BF16(c, a, b0, b1) \
    asm volatile("mma.sync.aligned.m16n8k16.row.col.f32.bf16.bf16.f32 " \
                 "{%0,%1,%2,%3}, {%4,%5,%6,%7}, {%8,%9}, {%0,%1,%2,%3};" \
                 : "+f"((c)[0]), "+f"((c)[1]), "+f"((c)[2]), "+f"((c)[3]) \
                 : "r"((a)[0]), "r"((a)[1]), "r"((a)[2]), "r"((a)[3]), "r"(b0), "r"(b1))

// ================= split-bf16 mma.sync GEMM =================
// C[M x 256] = A[M x 256] @ W[256 x 256] + bias
// Tile: BM=128, BN=128, BK=32. 256 threads = 8 warps (4 M x 2 N), warp tile 32x64.
// A = Ah + Al, W = Bh + Bl (bf16): D = Ah*Bh + Ah*Bl + Al*Bh, fp32 accumulate.
#define SA 40    // A smem row stride (elements): 80 B -> conflict-free ldmatrix
#define SB 136   // B smem row stride (elements): 272 B -> conflict-free ldmatrix

__global__ __launch_bounds__(256) void k_mma_gemm(
    const float* __restrict__ A, const float* __restrict__ W,
    const float* __restrict__ bias, float* __restrict__ C, int M)
{
    __shared__ __nv_bfloat16 sAh[128 * SA];
    __shared__ __nv_bfloat16 sAl[128 * SA];
    __shared__ __nv_bfloat16 sBh[32 * SB];
    __shared__ __nv_bfloat16 sBl[32 * SB];
    __shared__ float sbias[128];

    const int tid = threadIdx.x, wid = tid >> 5, lane = tid & 31;
    const int m0 = blockIdx.x * 128, n0 = blockIdx.y * 128;
    const int wm = wid & 3, wn = wid >> 2;          // warp: rows wm*32, cols wn*64

    if (tid < 128) sbias[tid] = bias[n0 + tid];

    const uint32_t bAh = smem_u32(sAh), bAl = smem_u32(sAl);
    const uint32_t bBh = smem_u32(sBh), bBl = smem_u32(sBl);

    float acc[2][8][4];
    #pragma unroll
    for (int mt = 0; mt < 2; mt++)
        #pragma unroll
        for (int nt = 0; nt < 8; nt++)
            #pragma unroll
            for (int q = 0; q < 4; q++) acc[mt][nt][q] = 0.0f;

    const int a_row = wm * 32 + (lane & 15);        // + mt*16
    const int a_koff = (lane >> 4) << 3;            // 0 or 8
    const int b_krow = lane & 15;                   // + kk

    for (int c = 0; c < 8; c++) {
        const int k0 = c * 32;
        __syncthreads();   // previous chunk's reads complete before overwrite

        // ---- A chunk: 128 rows x 32 k (1024 float4, 4 per thread) ----
        #pragma unroll
        for (int j = 0; j < 4; j++) {
            int idx = tid + 256 * j;
            int row = idx >> 3, kq = idx & 7;
            int gm = m0 + row;
            float4 a = make_float4(0.f, 0.f, 0.f, 0.f);
            if (gm < M) a = *(const float4*)(A + (size_t)gm * 256 + k0 + kq * 4);
            float hx = __bfloat162float(__float2bfloat16(a.x));
            float hy = __bfloat162float(__float2bfloat16(a.y));
            float hz = __bfloat162float(__float2bfloat16(a.z));
            float hw = __bfloat162float(__float2bfloat16(a.w));
            uint32_t off = (uint32_t)(row * SA + kq * 4) * 2u;
            *(uint32_t*)((char*)sAh + off)     = pack2(a.x, a.y);
            *(uint32_t*)((char*)sAh + off + 4) = pack2(a.z, a.w);
            *(uint32_t*)((char*)sAl + off)     = pack2(a.x - hx, a.y - hy);
            *(uint32_t*)((char*)sAl + off + 4) = pack2(a.z - hz, a.w - hw);
        }
        // ---- B chunk: 32 k-rows x 128 n (1024 float4, 4 per thread) ----
        #pragma unroll
        for (int j = 0; j < 4; j++) {
            int idx = tid + 256 * j;
            int kr = idx >> 5, nq = idx & 31;
            float4 w = *(const float4*)(W + (size_t)(k0 + kr) * 256 + n0 + nq * 4);
            float hx = __bfloat162float(__float2bfloat16(w.x));
            float hy = __bfloat162float(__float2bfloat16(w.y));
            float hz = __bfloat162float(__float2bfloat16(w.z));
            float hw = __bfloat162float(__float2bfloat16(w.w));
            uint32_t off = (uint32_t)(kr * SB + nq * 4) * 2u;
            *(uint32_t*)((char*)sBh + off)     = pack2(w.x, w.y);
            *(uint32_t*)((char*)sBh + off + 4) = pack2(w.z, w.w);
            *(uint32_t*)((char*)sBl + off)     = pack2(w.x - hx, w.y - hy);
            *(uint32_t*)((char*)sBl + off + 4) = pack2(w.z - hz, w.w - hw);
        }
        __syncthreads();

        // ---- compute: 2 k16 steps ----
        #pragma unroll
        for (int ks = 0; ks < 2; ks++) {
            const int kk = ks * 16;
            uint32_t aH[2][4], aL[2][4];
            #pragma unroll
            for (int mt = 0; mt < 2; mt++) {
                uint32_t offA = (uint32_t)((a_row + mt * 16) * SA + kk + a_koff) * 2u;
                LDSM_X4(aH[mt][0], aH[mt][1], aH[mt][2], aH[mt][3], bAh + offA);
                LDSM_X4(aL[mt][0], aL[mt][1], aL[mt][2], aL[mt][3], bAl + offA);
            }
            #pragma unroll
            for (int nt = 0; nt < 8; nt++) {
                uint32_t offB = (uint32_t)((kk + b_krow) * SB + wn * 64 + nt * 8) * 2u;
                uint32_t bh0, bh1, bl0, bl1;
                LDSM_X2T(bh0, bh1, bBh + offB);
                LDSM_X2T(bl0, bl1, bBl + offB);
                MMA_BF16(acc[0][nt], aH[0], bh0, bh1);
                MMA_BF16(acc[1][nt], aH[1], bh0, bh1);
                MMA_BF16(acc[0][nt], aH[0], bl0, bl1);
                MMA_BF16(acc[1][nt], aH[1], bl0, bl1);
                MMA_BF16(acc[0][nt], aL[0], bh0, bh1);
                MMA_BF16(acc[1][nt], aL[1], bh0, bh1);
            }
        }
    }

    // ---- epilogue ----
    const int rb = m0 + wm * 32, cb = wn * 64;      // cb relative to n0
    #pragma unroll
    for (int mt = 0; mt < 2; mt++) {
        int r = rb + mt * 16 + (lane >> 2);
        #pragma unroll
        for (int nt = 0; nt < 8; nt++) {
            int cc = cb + nt * 8 + (lane & 3) * 2;  // 0..127
            float b0 = sbias[cc], b1 = sbias[cc + 1];
            if (r < M) {
                float2 o = make_float2(acc[mt][nt][0] + b0, acc[mt][nt][1] + b1);
                *(float2*)(C + (size_t)r * 256 + n0 + cc) = o;
            }
            if (r + 8 < M) {
                float2 o = make_float2(acc[mt][nt][2] + b0, acc[mt][nt][3] + b1);
                *(float2*)(C + (size_t)(r + 8) * 256 + n0 + cc) = o;
            }
        }
    }
}

// ---------------- degree / dinv ----------------
__global__ void k_zero_deg() {
    int i = blockIdx.x * blockDim.x + threadIdx.x;
    if (i < NN) g_deg[i] = 0;
}
__global__ void k_count(const int* __restrict__ row) {
    int e = blockIdx.x * blockDim.x + threadIdx.x;
    if (e < NE) atomicAdd(&g_deg[row[e]], 1);
}
__global__ void k_dinv() {
    int i = blockIdx.x * blockDim.x + threadIdx.x;
    if (i < NN) g_dinv[i] = rsqrtf((float)g_deg[i] + 1.0f);
}

// ---------------- zero agg (self-loop folded into k_combine) ----------------
__global__ void k_zero_agg() {
    int idx = blockIdx.x * blockDim.x + threadIdx.x;
    if (idx < NN * 64)
        ((float4*)g_agg)[idx] = make_float4(0.f, 0.f, 0.f, 0.f);
}

// ---------------- edge scatter ----------------
__global__ void k_scatter(const int* __restrict__ row, const int* __restrict__ col) {
    int gw = (blockIdx.x * blockDim.x + threadIdx.x) >> 5;
    int lane = threadIdx.x & 31;
    if (gw >= NE) return;
    int r = __ldg(row + gw);
    int c = __ldg(col + gw);
    float s = g_dinv[r] * g_dinv[c];
    const float4* src = (const float4*)g_nb + (size_t)c * 64;
    float4* dst = (float4*)g_agg + (size_t)r * 64;
    #pragma unroll
    for (int h = 0; h < 2; h++) {
        float4 v = __ldg(src + lane + h * 32);
        v.x *= s; v.y *= s; v.z *= s; v.w *= s;
        asm volatile("red.global.add.v4.f32 [%0], {%1, %2, %3, %4};"
                     :: "l"(dst + lane + h * 32),
                        "f"(v.x), "f"(v.y), "f"(v.z), "f"(v.w)
                     : "memory");
    }
}

// ---------------- combine + self-loop + residual + L2 normalize + relu ----------------
__global__ __launch_bounds__(256) void k_combine() {
    int i = blockIdx.x;
    int t = threadIdx.x;
    size_t idx = (size_t)i * 256 + t;
    float di = g_dinv[i];
    float sl = di * di;
    float nbv = g_nb[idx];
    float v = g_h1[idx] + 0.5f * (g_agg[idx] + sl * nbv) + 0.5f * nbv;

    float ss = v * v;
    #pragma unroll
    for (int o = 16; o; o >>= 1) ss += __shfl_xor_sync(0xffffffffu, ss, o);

    __shared__ float ws[8];
    __shared__ float sscale;
    if ((t & 31) == 0) ws[t >> 5] = ss;
    __syncthreads();
    if (t == 0) {
        float s = ws[0] + ws[1] + ws[2] + ws[3] + ws[4] + ws[5] + ws[6] + ws[7];
        sscale = 1.0f / fmaxf(sqrtf(s), 1e-12f);
    }
    __syncthreads();
    g_h[idx] = fmaxf(v * sscale, 0.0f);
}

// ---------------- final 256->32 GEMM ----------------
__global__ __launch_bounds__(256) void k_final(
    const float* __restrict__ W2, const float* __restrict__ b2,
    float* __restrict__ out, int M)
{
    __shared__ float Ws[256 * 32];
    int tid = threadIdx.x;
    #pragma unroll
    for (int i = 0; i < 8; i++)
        ((float4*)Ws)[tid + i * 256] = ((const float4*)W2)[tid + i * 256];
    __syncthreads();

    int r = blockIdx.x * 64 + (tid >> 2);
    int cg = (tid & 3) * 8;
    if (r >= M) return;

    const float4* Arow = (const float4*)(g_h + (size_t)r * 256);
    float acc[8];
    #pragma unroll
    for (int j = 0; j < 8; j++) acc[j] = 0.0f;

    #pragma unroll 4
    for (int k4 = 0; k4 < 64; k4++) {
        float4 a = __ldg(Arow + k4);
        float av[4] = {a.x, a.y, a.z, a.w};
        #pragma unroll
        for (int u = 0; u < 4; u++) {
            const float* wrow = Ws + (k4 * 4 + u) * 32 + cg;
            float4 w0 = *(const float4*)(wrow);
            float4 w1 = *(const float4*)(wrow + 4);
            acc[0] += av[u] * w0.x;
            acc[1] += av[u] * w0.y;
            acc[2] += av[u] * w0.z;
            acc[3] += av[u] * w0.w;
            acc[4] += av[u] * w1.x;
            acc[5] += av[u] * w1.y;
            acc[6] += av[u] * w1.z;
            acc[7] += av[u] * w1.w;
        }
    }
    float4 o0 = make_float4(acc[0] + __ldg(b2 + cg + 0), acc[1] + __ldg(b2 + cg + 1),
                            acc[2] + __ldg(b2 + cg + 2), acc[3] + __ldg(b2 + cg + 3));
    float4 o1 = make_float4(acc[4] + __ldg(b2 + cg + 4), acc[5] + __ldg(b2 + cg + 5),
                            acc[6] + __ldg(b2 + cg + 6), acc[7] + __ldg(b2 + cg + 7));
    float* op = out + (size_t)r * 32 + cg;
    *(float4*)(op)     = o0;
    *(float4*)(op + 4) = o1;
}

// ---------------- host ----------------
extern "C" void kernel_launch(void* const* d_in, const int* in_sizes, int n_in,
                              void* d_out, int out_size)
{
    const float* x   = (const float*)d_in[0];
    const int*   ei  = (const int*)d_in[1];
    const int*   row = ei;
    const int*   col = ei + NE;
    const float* W[2]  = {(const float*)d_in[2], (const float*)d_in[6]};
    const float* bW[2] = {(const float*)d_in[3], (const float*)d_in[7]};
    const float* Wn[2] = {(const float*)d_in[4], (const float*)d_in[8]};
    const float* bn[2] = {(const float*)d_in[5], (const float*)d_in[9]};
    const float* W2 = (const float*)d_in[10];
    const float* b2 = (const float*)d_in[11];
    float* out = (float*)d_out;

    float *h1, *nb, *h;
    cudaGetSymbolAddress((void**)&h1, g_h1);
    cudaGetSymbolAddress((void**)&nb, g_nb);
    cudaGetSymbolAddress((void**)&h,  g_h);

    k_zero_deg<<<(NN + 255) / 256, 256>>>();
    k_count<<<(NE + 255) / 256, 256>>>(row);
    k_dinv<<<(NN + 255) / 256, 256>>>();

    const float* hin = x;
    dim3 gg((NN + 127) / 128, 2);
    for (int l = 0; l < 2; l++) {
        k_mma_gemm<<<gg, 256>>>(hin, W[l], bW[l], h1, NN);
        k_zero_agg<<<(NN * 64 + 255) / 256, 256>>>();
        k_mma_gemm<<<gg, 256>>>(h1, Wn[l], bn[l], nb, NN);
        k_scatter<<<(NE * 32 + 255) / 256, 256>>>(row, col);
        k_combine<<<NN, 256>>>();
        hin = h;
    }
    k_final<<<(NN + 63) / 64, 256>>>(W2, b2, out, NN);
}

// round 15
// speedup vs baseline: 1.5564x; 1.1997x over previous
#include <cuda_runtime.h>
#include <cuda_bf16.h>
#include <cstdint>

#define NN 50000
#define NE 800000
#define DD 256
#define OO 32

// ---------------- scratch ----------------
__device__ float g_h1[NN * DD];
__device__ float g_nb[NN * DD];
__device__ float g_agg[NN * DD];
__device__ float g_h[NN * DD];
__device__ float g_dinv[NN];
__device__ int   g_deg[NN];

// ================= helpers =================
__device__ __forceinline__ uint32_t smem_u32(const void* p) {
    uint32_t a;
    asm("{ .reg .u64 t; cvta.to.shared.u64 t, %1; cvt.u32.u64 %0, t; }" : "=r"(a) : "l"(p));
    return a;
}
__device__ __forceinline__ uint32_t pack2(float a, float b) {
    __nv_bfloat162 h = __floats2bfloat162_rn(a, b);
    return *(uint32_t*)&h;
}

#define LDSM_X4(r0, r1, r2, r3, addr) \
    asm volatile("ldmatrix.sync.aligned.m8n8.x4.shared.b16 {%0,%1,%2,%3}, [%4];" \
                 : "=r"(r0), "=r"(r1), "=r"(r2), "=r"(r3) : "r"(addr))
#define LDSM_X2T(r0, r1, addr) \
    asm volatile("ldmatrix.sync.aligned.m8n8.x2.trans.shared.b16 {%0,%1}, [%2];" \
                 : "=r"(r0), "=r"(r1) : "r"(addr))
#define MMA_BF16(c, a, b0, b1) \
    asm volatile("mma.sync.aligned.m16n8k16.row.col.f32.bf16.bf16.f32 " \
                 "{%0,%1,%2,%3}, {%4,%5,%6,%7}, {%8,%9}, {%0,%1,%2,%3};" \
                 : "+f"((c)[0]), "+f"((c)[1]), "+f"((c)[2]), "+f"((c)[3]) \
                 : "r"((a)[0]), "r"((a)[1]), "r"((a)[2]), "r"((a)[3]), "r"(b0), "r"(b1))

// ================= split-bf16 mma.sync GEMM =================
// C[M x 256] = A[M x 256] @ W[256 x 256] + bias
// Tile: BM=128, BN=128, BK=32. 256 threads = 8 warps (4 M x 2 N), warp tile 32x64.
// A = Ah + Al, W = Bh + Bl (bf16): D = Ah*Bh + Ah*Bl + Al*Bh, fp32 accumulate.
// __launch_bounds__(256,2): cap regs at 128 so 2 CTAs/SM co-reside and the
// load/convert phase of one CTA overlaps the MMA phase of the other.
#define SA 40    // A smem row stride (elements): 80 B -> conflict-free ldmatrix
#define SB 136   // B smem row stride (elements): 272 B -> conflict-free ldmatrix

__global__ __launch_bounds__(256, 2) void k_mma_gemm(
    const float* __restrict__ A, const float* __restrict__ W,
    const float* __restrict__ bias, float* __restrict__ C, int M)
{
    __shared__ __nv_bfloat16 sAh[128 * SA];
    __shared__ __nv_bfloat16 sAl[128 * SA];
    __shared__ __nv_bfloat16 sBh[32 * SB];
    __shared__ __nv_bfloat16 sBl[32 * SB];
    __shared__ float sbias[128];

    const int tid = threadIdx.x, wid = tid >> 5, lane = tid & 31;
    const int m0 = blockIdx.x * 128, n0 = blockIdx.y * 128;
    const int wm = wid & 3, wn = wid >> 2;          // warp: rows wm*32, cols wn*64

    if (tid < 128) sbias[tid] = bias[n0 + tid];

    const uint32_t bAh = smem_u32(sAh), bAl = smem_u32(sAl);
    const uint32_t bBh = smem_u32(sBh), bBl = smem_u32(sBl);

    float acc[2][8][4];
    #pragma unroll
    for (int mt = 0; mt < 2; mt++)
        #pragma unroll
        for (int nt = 0; nt < 8; nt++)
            #pragma unroll
            for (int q = 0; q < 4; q++) acc[mt][nt][q] = 0.0f;

    const int a_row = wm * 32 + (lane & 15);        // + mt*16
    const int a_koff = (lane >> 4) << 3;            // 0 or 8
    const int b_krow = lane & 15;                   // + kk

    for (int c = 0; c < 8; c++) {
        const int k0 = c * 32;
        __syncthreads();   // previous chunk's reads complete before overwrite

        // ---- A chunk: 128 rows x 32 k (1024 float4, 4 per thread) ----
        #pragma unroll
        for (int j = 0; j < 4; j++) {
            int idx = tid + 256 * j;
            int row = idx >> 3, kq = idx & 7;
            int gm = m0 + row;
            float4 a = make_float4(0.f, 0.f, 0.f, 0.f);
            if (gm < M) a = *(const float4*)(A + (size_t)gm * 256 + k0 + kq * 4);
            float hx = __bfloat162float(__float2bfloat16(a.x));
            float hy = __bfloat162float(__float2bfloat16(a.y));
            float hz = __bfloat162float(__float2bfloat16(a.z));
            float hw = __bfloat162float(__float2bfloat16(a.w));
            uint32_t off = (uint32_t)(row * SA + kq * 4) * 2u;
            *(uint32_t*)((char*)sAh + off)     = pack2(a.x, a.y);
            *(uint32_t*)((char*)sAh + off + 4) = pack2(a.z, a.w);
            *(uint32_t*)((char*)sAl + off)     = pack2(a.x - hx, a.y - hy);
            *(uint32_t*)((char*)sAl + off + 4) = pack2(a.z - hz, a.w - hw);
        }
        // ---- B chunk: 32 k-rows x 128 n (1024 float4, 4 per thread) ----
        #pragma unroll
        for (int j = 0; j < 4; j++) {
            int idx = tid + 256 * j;
            int kr = idx >> 5, nq = idx & 31;
            float4 w = *(const float4*)(W + (size_t)(k0 + kr) * 256 + n0 + nq * 4);
            float hx = __bfloat162float(__float2bfloat16(w.x));
            float hy = __bfloat162float(__float2bfloat16(w.y));
            float hz = __bfloat162float(__float2bfloat16(w.z));
            float hw = __bfloat162float(__float2bfloat16(w.w));
            uint32_t off = (uint32_t)(kr * SB + nq * 4) * 2u;
            *(uint32_t*)((char*)sBh + off)     = pack2(w.x, w.y);
            *(uint32_t*)((char*)sBh + off + 4) = pack2(w.z, w.w);
            *(uint32_t*)((char*)sBl + off)     = pack2(w.x - hx, w.y - hy);
            *(uint32_t*)((char*)sBl + off + 4) = pack2(w.z - hz, w.w - hw);
        }
        __syncthreads();

        // ---- compute: 2 k16 steps ----
        #pragma unroll
        for (int ks = 0; ks < 2; ks++) {
            const int kk = ks * 16;
            uint32_t aH[2][4], aL[2][4];
            #pragma unroll
            for (int mt = 0; mt < 2; mt++) {
                uint32_t offA = (uint32_t)((a_row + mt * 16) * SA + kk + a_koff) * 2u;
                LDSM_X4(aH[mt][0], aH[mt][1], aH[mt][2], aH[mt][3], bAh + offA);
                LDSM_X4(aL[mt][0], aL[mt][1], aL[mt][2], aL[mt][3], bAl + offA);
            }
            #pragma unroll
            for (int nt = 0; nt < 8; nt++) {
                uint32_t offB = (uint32_t)((kk + b_krow) * SB + wn * 64 + nt * 8) * 2u;
                uint32_t bh0, bh1, bl0, bl1;
                LDSM_X2T(bh0, bh1, bBh + offB);
                LDSM_X2T(bl0, bl1, bBl + offB);
                MMA_BF16(acc[0][nt], aH[0], bh0, bh1);
                MMA_BF16(acc[1][nt], aH[1], bh0, bh1);
                MMA_BF16(acc[0][nt], aH[0], bl0, bl1);
                MMA_BF16(acc[1][nt], aH[1], bl0, bl1);
                MMA_BF16(acc[0][nt], aL[0], bh0, bh1);
                MMA_BF16(acc[1][nt], aL[1], bh0, bh1);
            }
        }
    }

    // ---- epilogue ----
    const int rb = m0 + wm * 32, cb = wn * 64;      // cb relative to n0
    #pragma unroll
    for (int mt = 0; mt < 2; mt++) {
        int r = rb + mt * 16 + (lane >> 2);
        #pragma unroll
        for (int nt = 0; nt < 8; nt++) {
            int cc = cb + nt * 8 + (lane & 3) * 2;  // 0..127
            float b0 = sbias[cc], b1 = sbias[cc + 1];
            if (r < M) {
                float2 o = make_float2(acc[mt][nt][0] + b0, acc[mt][nt][1] + b1);
                *(float2*)(C + (size_t)r * 256 + n0 + cc) = o;
            }
            if (r + 8 < M) {
                float2 o = make_float2(acc[mt][nt][2] + b0, acc[mt][nt][3] + b1);
                *(float2*)(C + (size_t)(r + 8) * 256 + n0 + cc) = o;
            }
        }
    }
}

// ---------------- degree / dinv ----------------
__global__ void k_zero_deg() {
    int i = blockIdx.x * blockDim.x + threadIdx.x;
    if (i < NN) g_deg[i] = 0;
}
__global__ void k_count(const int* __restrict__ row) {
    int e = blockIdx.x * blockDim.x + threadIdx.x;
    if (e < NE) atomicAdd(&g_deg[row[e]], 1);
}
__global__ void k_dinv() {
    int i = blockIdx.x * blockDim.x + threadIdx.x;
    if (i < NN) g_dinv[i] = rsqrtf((float)g_deg[i] + 1.0f);
}

// ---------------- zero agg (self-loop folded into k_combine) ----------------
__global__ void k_zero_agg() {
    int idx = blockIdx.x * blockDim.x + threadIdx.x;
    if (idx < NN * 64)
        ((float4*)g_agg)[idx] = make_float4(0.f, 0.f, 0.f, 0.f);
}

// ---------------- edge scatter ----------------
__global__ void k_scatter(const int* __restrict__ row, const int* __restrict__ col) {
    int gw = (blockIdx.x * blockDim.x + threadIdx.x) >> 5;
    int lane = threadIdx.x & 31;
    if (gw >= NE) return;
    int r = __ldg(row + gw);
    int c = __ldg(col + gw);
    float s = g_dinv[r] * g_dinv[c];
    const float4* src = (const float4*)g_nb + (size_t)c * 64;
    float4* dst = (float4*)g_agg + (size_t)r * 64;
    #pragma unroll
    for (int h = 0; h < 2; h++) {
        float4 v = __ldg(src + lane + h * 32);
        v.x *= s; v.y *= s; v.z *= s; v.w *= s;
        asm volatile("red.global.add.v4.f32 [%0], {%1, %2, %3, %4};"
                     :: "l"(dst + lane + h * 32),
                        "f"(v.x), "f"(v.y), "f"(v.z), "f"(v.w)
                     : "memory");
    }
}

// ---------------- combine + self-loop + residual + L2 normalize + relu ----------------
__global__ __launch_bounds__(256) void k_combine() {
    int i = blockIdx.x;
    int t = threadIdx.x;
    size_t idx = (size_t)i * 256 + t;
    float di = g_dinv[i];
    float sl = di * di;
    float nbv = g_nb[idx];
    float v = g_h1[idx] + 0.5f * (g_agg[idx] + sl * nbv) + 0.5f * nbv;

    float ss = v * v;
    #pragma unroll
    for (int o = 16; o; o >>= 1) ss += __shfl_xor_sync(0xffffffffu, ss, o);

    __shared__ float ws[8];
    __shared__ float sscale;
    if ((t & 31) == 0) ws[t >> 5] = ss;
    __syncthreads();
    if (t == 0) {
        float s = ws[0] + ws[1] + ws[2] + ws[3] + ws[4] + ws[5] + ws[6] + ws[7];
        sscale = 1.0f / fmaxf(sqrtf(s), 1e-12f);
    }
    __syncthreads();
    g_h[idx] = fmaxf(v * sscale, 0.0f);
}

// ---------------- final 256->32 GEMM ----------------
__global__ __launch_bounds__(256) void k_final(
    const float* __restrict__ W2, const float* __restrict__ b2,
    float* __restrict__ out, int M)
{
    __shared__ float Ws[256 * 32];
    int tid = threadIdx.x;
    #pragma unroll
    for (int i = 0; i < 8; i++)
        ((float4*)Ws)[tid + i * 256] = ((const float4*)W2)[tid + i * 256];
    __syncthreads();

    int r = blockIdx.x * 64 + (tid >> 2);
    int cg = (tid & 3) * 8;
    if (r >= M) return;

    const float4* Arow = (const float4*)(g_h + (size_t)r * 256);
    float acc[8];
    #pragma unroll
    for (int j = 0; j < 8; j++) acc[j] = 0.0f;

    #pragma unroll 4
    for (int k4 = 0; k4 < 64; k4++) {
        float4 a = __ldg(Arow + k4);
        float av[4] = {a.x, a.y, a.z, a.w};
        #pragma unroll
        for (int u = 0; u < 4; u++) {
            const float* wrow = Ws + (k4 * 4 + u) * 32 + cg;
            float4 w0 = *(const float4*)(wrow);
            float4 w1 = *(const float4*)(wrow + 4);
            acc[0] += av[u] * w0.x;
            acc[1] += av[u] * w0.y;
            acc[2] += av[u] * w0.z;
            acc[3] += av[u] * w0.w;
            acc[4] += av[u] * w1.x;
            acc[5] += av[u] * w1.y;
            acc[6] += av[u] * w1.z;
            acc[7] += av[u] * w1.w;
        }
    }
    float4 o0 = make_float4(acc[0] + __ldg(b2 + cg + 0), acc[1] + __ldg(b2 + cg + 1),
                            acc[2] + __ldg(b2 + cg + 2), acc[3] + __ldg(b2 + cg + 3));
    float4 o1 = make_float4(acc[4] + __ldg(b2 + cg + 4), acc[5] + __ldg(b2 + cg + 5),
                            acc[6] + __ldg(b2 + cg + 6), acc[7] + __ldg(b2 + cg + 7));
    float* op = out + (size_t)r * 32 + cg;
    *(float4*)(op)     = o0;
    *(float4*)(op + 4) = o1;
}

// ---------------- host ----------------
extern "C" void kernel_launch(void* const* d_in, const int* in_sizes, int n_in,
                              void* d_out, int out_size)
{
    const float* x   = (const float*)d_in[0];
    const int*   ei  = (const int*)d_in[1];
    const int*   row = ei;
    const int*   col = ei + NE;
    const float* W[2]  = {(const float*)d_in[2], (const float*)d_in[6]};
    const float* bW[2] = {(const float*)d_in[3], (const float*)d_in[7]};
    const float* Wn[2] = {(const float*)d_in[4], (const float*)d_in[8]};
    const float* bn[2] = {(const float*)d_in[5], (const float*)d_in[9]};
    const float* W2 = (const float*)d_in[10];
    const float* b2 = (const float*)d_in[11];
    float* out = (float*)d_out;

    float *h1, *nb, *h;
    cudaGetSymbolAddress((void**)&h1, g_h1);
    cudaGetSymbolAddress((void**)&nb, g_nb);
    cudaGetSymbolAddress((void**)&h,  g_h);

    k_zero_deg<<<(NN + 255) / 256, 256>>>();
    k_count<<<(NE + 255) / 256, 256>>>(row);
    k_dinv<<<(NN + 255) / 256, 256>>>();

    const float* hin = x;
    dim3 gg((NN + 127) / 128, 2);
    for (int l = 0; l < 2; l++) {
        k_mma_gemm<<<gg, 256>>>(hin, W[l], bW[l], h1, NN);
        k_zero_agg<<<(NN * 64 + 255) / 256, 256>>>();
        k_mma_gemm<<<gg, 256>>>(h1, Wn[l], bn[l], nb, NN);
        k_scatter<<<(NE * 32 + 255) / 256, 256>>>(row, col);
        k_combine<<<NN, 256>>>();
        hin = h;
    }
    k_final<<<(NN + 63) / 64, 256>>>(W2, b2, out, NN);
}